// round 1
// baseline (speedup 1.0000x reference)
#include <cuda_runtime.h>
#include <cuda_bf16.h>
#include <mma.h>

using namespace nvcuda;

// Problem constants (fixed shapes from reference setup_inputs)
#define B_  2
#define L_  512
#define D_  256
#define KP  768   // 3*D : [hi*hi | hi*lo | lo*hi] split-bf16 concatenation

// Scratch (device globals — no allocation allowed in kernel_launch)
__device__ __nv_bfloat16 g_A[B_ * L_ * KP];   // (x*w1) split, rows = (b,i)
__device__ __nv_bfloat16 g_B[B_ * L_ * KP];   // x split,      rows = (b,j)

// ---------------------------------------------------------------------------
// Prep: build split-bf16 operands.
//   a = x*w1 ; a_hi = bf16(a) ; a_lo = bf16(a - a_hi)
//   x_hi = bf16(x) ; x_lo = bf16(x - x_hi)
//   A' row = [a_hi (0:256) | a_hi (256:512) | a_lo (512:768)]
//   B' row = [x_hi         | x_lo           | x_hi          ]
// so  A'·B'ᵀ over K=768 = a_hi*x_hi + a_hi*x_lo + a_lo*x_hi  ≈ a*x (rel ~2^-18)
// ---------------------------------------------------------------------------
__global__ void prep_kernel(const float* __restrict__ x,
                            const float* __restrict__ W) {
    int idx = blockIdx.x * blockDim.x + threadIdx.x;   // over B*L*D
    if (idx >= B_ * L_ * D_) return;
    int d  = idx % D_;
    int bi = idx / D_;            // b*L + i

    float xv = x[idx];
    float w1 = W[d];              // W[:D, 0]
    float a  = xv * w1;

    __nv_bfloat16 ahi = __float2bfloat16(a);
    __nv_bfloat16 alo = __float2bfloat16(a  - __bfloat162float(ahi));
    __nv_bfloat16 xhi = __float2bfloat16(xv);
    __nv_bfloat16 xlo = __float2bfloat16(xv - __bfloat162float(xhi));

    __nv_bfloat16* Arow = g_A + (size_t)bi * KP;
    __nv_bfloat16* Brow = g_B + (size_t)bi * KP;
    Arow[d]         = ahi;
    Arow[D_ + d]    = ahi;
    Arow[2*D_ + d]  = alo;
    Brow[d]         = xhi;
    Brow[D_ + d]    = xlo;
    Brow[2*D_ + d]  = xhi;
}

// ---------------------------------------------------------------------------
// GEMM: out[b, i, j] = A'[b,i,:] · B'[b,j,:] + bias
// 64x64 output tile per CTA, 4 warps (2x2), each warp owns 32x32 (2x2 wmma).
// ---------------------------------------------------------------------------
#define TILE     64
#define KC       64
#define SSTRIDE  72   // 64 + 8 bf16 pad (144B rows) to dodge bank conflicts

__global__ __launch_bounds__(128)
void gemm_kernel(const float* __restrict__ bias_p, float* __restrict__ out) {
    __shared__ __nv_bfloat16 sA[TILE * SSTRIDE];
    __shared__ __nv_bfloat16 sB[TILE * SSTRIDE];

    const int bz  = blockIdx.z;             // batch
    const int ti  = blockIdx.y;             // i-tile
    const int tj  = blockIdx.x;             // j-tile
    const int tid = threadIdx.x;
    const int warp = tid >> 5;
    const int wr = warp >> 1;               // warp row (0..1)
    const int wc = warp & 1;                // warp col (0..1)

    const __nv_bfloat16* Abase = g_A + (size_t)(bz * L_ + ti * TILE) * KP;
    const __nv_bfloat16* Bbase = g_B + (size_t)(bz * L_ + tj * TILE) * KP;

    wmma::fragment<wmma::accumulator, 16, 16, 16, float> acc[2][2];
    #pragma unroll
    for (int r = 0; r < 2; r++)
        #pragma unroll
        for (int c = 0; c < 2; c++)
            wmma::fill_fragment(acc[r][c], 0.0f);

    for (int kc = 0; kc < KP; kc += KC) {
        // cooperative tile load: 64 rows x 64 bf16 = 512 uint4 per matrix
        #pragma unroll
        for (int t = tid; t < TILE * (KC / 8); t += 128) {
            int row = t >> 3;
            int v   = t & 7;
            const uint4* srcA = reinterpret_cast<const uint4*>(Abase + (size_t)row * KP + kc) + v;
            const uint4* srcB = reinterpret_cast<const uint4*>(Bbase + (size_t)row * KP + kc) + v;
            *reinterpret_cast<uint4*>(&sA[row * SSTRIDE + v * 8]) = *srcA;
            *reinterpret_cast<uint4*>(&sB[row * SSTRIDE + v * 8]) = *srcB;
        }
        __syncthreads();

        #pragma unroll
        for (int kk = 0; kk < KC; kk += 16) {
            wmma::fragment<wmma::matrix_a, 16, 16, 16, __nv_bfloat16, wmma::row_major> af[2];
            wmma::fragment<wmma::matrix_b, 16, 16, 16, __nv_bfloat16, wmma::col_major> bf[2];
            #pragma unroll
            for (int r = 0; r < 2; r++)
                wmma::load_matrix_sync(af[r], &sA[(wr * 32 + r * 16) * SSTRIDE + kk], SSTRIDE);
            #pragma unroll
            for (int c = 0; c < 2; c++)
                wmma::load_matrix_sync(bf[c], &sB[(wc * 32 + c * 16) * SSTRIDE + kk], SSTRIDE);
            #pragma unroll
            for (int r = 0; r < 2; r++)
                #pragma unroll
                for (int c = 0; c < 2; c++)
                    wmma::mma_sync(acc[r][c], af[r], bf[c], acc[r][c]);
        }
        __syncthreads();
    }

    const float bias = bias_p[0];
    #pragma unroll
    for (int r = 0; r < 2; r++) {
        #pragma unroll
        for (int c = 0; c < 2; c++) {
            #pragma unroll
            for (int t = 0; t < acc[r][c].num_elements; t++)
                acc[r][c].x[t] += bias;
            int gi = ti * TILE + wr * 32 + r * 16;
            int gj = tj * TILE + wc * 32 + c * 16;
            float* dst = out + (size_t)bz * L_ * L_ + (size_t)gi * L_ + gj;
            wmma::store_matrix_sync(dst, acc[r][c], L_, wmma::mem_row_major);
        }
    }
}

// ---------------------------------------------------------------------------
// kernel_launch
//   d_in[0] = inputs  f32 (2,512,256)
//   d_in[1] = W       f32 (512,1)
//   d_in[2] = b       f32 (1,)
//   d_out   = f32 (2,512,512,1)
// ---------------------------------------------------------------------------
extern "C" void kernel_launch(void* const* d_in, const int* in_sizes, int n_in,
                              void* d_out, int out_size) {
    const float* x    = (const float*)d_in[0];
    const float* W    = (const float*)d_in[1];
    const float* bptr = (const float*)d_in[2];
    float* out = (float*)d_out;

    const int total = B_ * L_ * D_;
    prep_kernel<<<(total + 255) / 256, 256>>>(x, W);

    dim3 grid(L_ / TILE, L_ / TILE, B_);   // (8, 8, 2)
    gemm_kernel<<<grid, 128>>>(bptr, out);
}

// round 2
// speedup vs baseline: 1.7672x; 1.7672x over previous
#include <cuda_runtime.h>
#include <cuda_bf16.h>
#include <mma.h>

using namespace nvcuda;

// Fixed shapes from reference setup_inputs
#define B_      2
#define L_      512
#define D_      256
#define TILE    64          // output tile (64x64 per CTA)
#define DC      64          // d-chunk width
#define NCH     (D_ / DC)   // 4 chunks
#define THREADS 256
#define SST     72          // smem row stride (bf16 elems): 64 + 8 pad

// out[b,i,j] = sum_d x[b,i,d]*w1[d]*x[b,j,d] + bias
// (antisymmetric lin_i - lin_j cancels under the (P+P^T)/2 symmetrization;
//  bilinear term is already symmetric; w2 = W[D:,0] is dead.)
//
// Precision: split-bf16 3-product trick per d-chunk:
//   a = x*w1 = ahi + alo (bf16 split), x = xhi + xlo
//   a*x ≈ ahi*xhi + ahi*xlo + alo*xhi   (error ~2^-16 relative)
__global__ __launch_bounds__(THREADS)
void fused_pairwise_kernel(const float* __restrict__ x,
                           const float* __restrict__ W,
                           const float* __restrict__ bias_p,
                           float* __restrict__ out) {
    __shared__ __align__(16) __nv_bfloat16 sAhi[TILE * SST];
    __shared__ __align__(16) __nv_bfloat16 sAlo[TILE * SST];
    __shared__ __align__(16) __nv_bfloat16 sBhi[TILE * SST];
    __shared__ __align__(16) __nv_bfloat16 sBlo[TILE * SST];
    __shared__ float sW[D_];

    const int bz  = blockIdx.z;
    const int ti  = blockIdx.y;
    const int tj  = blockIdx.x;
    const int tid = threadIdx.x;
    const int warp = tid >> 5;
    const int wr = warp >> 1;     // 0..3  (warp row: 16 rows each)
    const int wc = warp & 1;      // 0..1  (warp col: 32 cols each)

    // Preload w1 = W[:D,0] into smem
    if (tid < D_ / 4)
        ((float4*)sW)[tid] = ((const float4*)W)[tid];

    const float* Abase = x + (size_t)(bz * L_ + ti * TILE) * D_;
    const float* Bbase = x + (size_t)(bz * L_ + tj * TILE) * D_;

    // Per-thread gmem mapping: 4 float4 per matrix per chunk.
    // lin = i*256 + tid ; row = lin>>4 (64 rows), c4 = lin&15 (16 float4/row)
    float4 ra[4], rb[4];
    #pragma unroll
    for (int i = 0; i < 4; i++) {
        int lin = i * THREADS + tid;
        int row = lin >> 4, c4 = lin & 15;
        ra[i] = ((const float4*)(Abase + (size_t)row * D_))[c4];
        rb[i] = ((const float4*)(Bbase + (size_t)row * D_))[c4];
    }
    __syncthreads();   // sW ready

    wmma::fragment<wmma::accumulator, 16, 16, 16, float> acc[2];
    wmma::fill_fragment(acc[0], 0.0f);
    wmma::fill_fragment(acc[1], 0.0f);

    for (int ch = 0; ch < NCH; ch++) {
        // ---- convert registers -> split bf16 smem ----
        #pragma unroll
        for (int i = 0; i < 4; i++) {
            int lin = i * THREADS + tid;
            int row = lin >> 4, c4 = lin & 15;
            int dbase = ch * DC + c4 * 4;

            float av[4] = {ra[i].x, ra[i].y, ra[i].z, ra[i].w};
            float bv[4] = {rb[i].x, rb[i].y, rb[i].z, rb[i].w};

            __nv_bfloat16 ah[4], al[4], bh[4], bl[4];
            #pragma unroll
            for (int j = 0; j < 4; j++) {
                float a = av[j] * sW[dbase + j];
                ah[j] = __float2bfloat16(a);
                al[j] = __float2bfloat16(a - __bfloat162float(ah[j]));
                bh[j] = __float2bfloat16(bv[j]);
                bl[j] = __float2bfloat16(bv[j] - __bfloat162float(bh[j]));
            }
            int off = row * SST + c4 * 4;   // elem offset, 8B aligned
            *(uint2*)&sAhi[off] = *(uint2*)ah;
            *(uint2*)&sAlo[off] = *(uint2*)al;
            *(uint2*)&sBhi[off] = *(uint2*)bh;
            *(uint2*)&sBlo[off] = *(uint2*)bl;
        }
        __syncthreads();

        // ---- prefetch next chunk's f32 while MMA runs ----
        if (ch + 1 < NCH) {
            #pragma unroll
            for (int i = 0; i < 4; i++) {
                int lin = i * THREADS + tid;
                int row = lin >> 4, c4 = lin & 15;
                ra[i] = ((const float4*)(Abase + (size_t)row * D_ + (ch + 1) * DC))[c4];
                rb[i] = ((const float4*)(Bbase + (size_t)row * D_ + (ch + 1) * DC))[c4];
            }
        }

        // ---- 3 MMA passes: Ahi*Bhi + Ahi*Blo + Alo*Bhi ----
        const __nv_bfloat16* pa[3] = {sAhi, sAhi, sAlo};
        const __nv_bfloat16* pb[3] = {sBhi, sBlo, sBhi};
        #pragma unroll
        for (int p = 0; p < 3; p++) {
            #pragma unroll
            for (int kk = 0; kk < DC; kk += 16) {
                wmma::fragment<wmma::matrix_a, 16, 16, 16, __nv_bfloat16, wmma::row_major> af;
                wmma::fragment<wmma::matrix_b, 16, 16, 16, __nv_bfloat16, wmma::col_major> bf0, bf1;
                wmma::load_matrix_sync(af,  pa[p] + (wr * 16) * SST + kk, SST);
                wmma::load_matrix_sync(bf0, pb[p] + (wc * 32) * SST + kk, SST);
                wmma::load_matrix_sync(bf1, pb[p] + (wc * 32 + 16) * SST + kk, SST);
                wmma::mma_sync(acc[0], af, bf0, acc[0]);
                wmma::mma_sync(acc[1], af, bf1, acc[1]);
            }
        }
        __syncthreads();
    }

    // ---- epilogue: add bias, store ----
    const float bias = bias_p[0];
    #pragma unroll
    for (int c = 0; c < 2; c++) {
        #pragma unroll
        for (int t = 0; t < acc[c].num_elements; t++)
            acc[c].x[t] += bias;
        int gi = ti * TILE + wr * 16;
        int gj = tj * TILE + wc * 32 + c * 16;
        float* dst = out + (size_t)bz * L_ * L_ + (size_t)gi * L_ + gj;
        wmma::store_matrix_sync(dst, acc[c], L_, wmma::mem_row_major);
    }
}

// ---------------------------------------------------------------------------
// d_in[0] = inputs f32 (2,512,256), d_in[1] = W f32 (512,1), d_in[2] = b f32 (1,)
// d_out   = f32 (2,512,512,1)
// ---------------------------------------------------------------------------
extern "C" void kernel_launch(void* const* d_in, const int* in_sizes, int n_in,
                              void* d_out, int out_size) {
    const float* x    = (const float*)d_in[0];
    const float* W    = (const float*)d_in[1];
    const float* bptr = (const float*)d_in[2];
    float* out = (float*)d_out;

    dim3 grid(L_ / TILE, L_ / TILE, B_);   // (8, 8, 2) = 128 CTAs
    fused_pairwise_kernel<<<grid, THREADS>>>(x, W, bptr, out);
}